// round 1
// baseline (speedup 1.0000x reference)
#include <cuda_runtime.h>
#include <math.h>

// Problem constants
#define BB 4
#define TT 2048
#define CC 1024
#define HH 16
#define DD 64
#define C3 3072          // 3*C
#define MTOT 8192        // B*T

// Scratch (device globals — no allocation allowed in kernel_launch)
__device__ float g_qkv[(size_t)MTOT * C3];   // [M, 3C] row-major: q | k | v per row
__device__ float g_att[(size_t)MTOT * CC];   // attention output [M, C]

// ---------------------------------------------------------------------------
// GEMM (NT): C[m,n] = sum_k A[m,k] * W[n,k]  (+ bias[n] if bias != nullptr)
// A: [M,K] row-major, W: [N,K] row-major. 128x128 block tile, BK=8,
// 8x8 per-thread microtile, 256 threads, register prefetch of next k-slab.
// ---------------------------------------------------------------------------
__global__ __launch_bounds__(256) void gemm_nt(
    const float* __restrict__ A, const float* __restrict__ W,
    float* __restrict__ C, const float* __restrict__ bias,
    int M, int N, int K)
{
    const int BK = 8;
    __shared__ float As[8][128];
    __shared__ float Ws[8][128];

    int tid  = threadIdx.x;
    int brow = blockIdx.y * 128;
    int bcol = blockIdx.x * 128;

    // cooperative load mapping: 128 rows x 8 k -> 256 threads x float4
    int lr = tid >> 1;           // tile row 0..127
    int lc = (tid & 1) * 4;      // k offset 0 or 4

    // microtile mapping: 16x16 thread grid, each 8x8
    int tm = (tid >> 4) * 8;
    int tn = (tid & 15) * 8;

    const float* Aptr = A + (size_t)(brow + lr) * K + lc;
    const float* Wptr = W + (size_t)(bcol + lr) * K + lc;

    float4 an = *(const float4*)Aptr;
    float4 wn = *(const float4*)Wptr;

    float acc[8][8];
#pragma unroll
    for (int i = 0; i < 8; i++)
#pragma unroll
        for (int j = 0; j < 8; j++) acc[i][j] = 0.0f;

    for (int k0 = 0; k0 < K; k0 += BK) {
        // stage current slab (transposed to k-major)
        As[lc + 0][lr] = an.x; As[lc + 1][lr] = an.y;
        As[lc + 2][lr] = an.z; As[lc + 3][lr] = an.w;
        Ws[lc + 0][lr] = wn.x; Ws[lc + 1][lr] = wn.y;
        Ws[lc + 2][lr] = wn.z; Ws[lc + 3][lr] = wn.w;
        __syncthreads();

        // prefetch next slab into registers (overlaps with compute)
        if (k0 + BK < K) {
            an = *(const float4*)(Aptr + k0 + BK);
            wn = *(const float4*)(Wptr + k0 + BK);
        }

#pragma unroll
        for (int k = 0; k < BK; k++) {
            float a[8], b[8];
            *(float4*)&a[0] = *(const float4*)&As[k][tm];
            *(float4*)&a[4] = *(const float4*)&As[k][tm + 4];
            *(float4*)&b[0] = *(const float4*)&Ws[k][tn];
            *(float4*)&b[4] = *(const float4*)&Ws[k][tn + 4];
#pragma unroll
            for (int i = 0; i < 8; i++)
#pragma unroll
                for (int j = 0; j < 8; j++)
                    acc[i][j] = fmaf(a[i], b[j], acc[i][j]);
        }
        __syncthreads();
    }

    // epilogue
#pragma unroll
    for (int i = 0; i < 8; i++) {
        size_t row = (size_t)(brow + tm + i);
#pragma unroll
        for (int j = 0; j < 8; j += 4) {
            float4 v;
            v.x = acc[i][j + 0]; v.y = acc[i][j + 1];
            v.z = acc[i][j + 2]; v.w = acc[i][j + 3];
            if (bias != nullptr) {
                v.x += bias[bcol + tn + j + 0];
                v.y += bias[bcol + tn + j + 1];
                v.z += bias[bcol + tn + j + 2];
                v.w += bias[bcol + tn + j + 3];
            }
            *(float4*)&C[row * N + bcol + tn + j] = v;
        }
    }
}

// ---------------------------------------------------------------------------
// Causal flash attention over the fused qkv buffer.
// Grid: (T/128, B*H). 128 threads/CTA, one query row per thread.
// Bc=32 key/value tile in smem, online softmax in registers.
// qkv row layout: [q(1024) | k(1024) | v(1024)], head slice = h*64.
// ---------------------------------------------------------------------------
__global__ __launch_bounds__(128) void flash_attn(
    const float* __restrict__ qkv, float* __restrict__ out)
{
    __shared__ float Ks[32][64];
    __shared__ float Vs[32][64];

    int tid = threadIdx.x;
    int qt  = blockIdx.x;
    int bh  = blockIdx.y;
    int b   = bh >> 4;
    int h   = bh & 15;
    int qrow = qt * 128 + tid;       // query token index within sequence

    const float qscale = 0.125f;     // 1/sqrt(64)

    // load this thread's q row (scaled)
    const float* qp = qkv + (size_t)(b * TT + qrow) * C3 + h * DD;
    float4 q4[16];
#pragma unroll
    for (int i = 0; i < 16; i++) {
        float4 v = *(const float4*)(qp + 4 * i);
        q4[i] = make_float4(v.x * qscale, v.y * qscale, v.z * qscale, v.w * qscale);
    }

    float4 o4[16];
#pragma unroll
    for (int i = 0; i < 16; i++) o4[i] = make_float4(0.f, 0.f, 0.f, 0.f);
    float m = -1e30f, l = 0.0f;

    int nkt = 4 * qt + 4;            // key tiles needed to cover causal span
    for (int kt = 0; kt < nkt; kt++) {
        // cooperative K/V tile load: 32 rows x 64 cols, float4 per thread x4
#pragma unroll
        for (int i = 0; i < 4; i++) {
            int idx = tid + i * 128;
            int row = idx >> 4;
            int c4  = (idx & 15) * 4;
            const float* base = qkv + (size_t)(b * TT + kt * 32 + row) * C3 + h * DD + c4;
            *(float4*)&Ks[row][c4] = *(const float4*)(base + CC);
            *(float4*)&Vs[row][c4] = *(const float4*)(base + 2 * CC);
        }
        __syncthreads();

        // scores for this tile
        float s[32];
        float mt = -1e30f;
        int kbase = kt * 32;
#pragma unroll 4
        for (int j = 0; j < 32; j++) {
            const float4* kr = (const float4*)Ks[j];
            float4 acc = make_float4(0.f, 0.f, 0.f, 0.f);
#pragma unroll
            for (int i = 0; i < 16; i++) {
                float4 kv = kr[i];
                acc.x = fmaf(q4[i].x, kv.x, acc.x);
                acc.y = fmaf(q4[i].y, kv.y, acc.y);
                acc.z = fmaf(q4[i].z, kv.z, acc.z);
                acc.w = fmaf(q4[i].w, kv.w, acc.w);
            }
            float sv = (acc.x + acc.y) + (acc.z + acc.w);
            sv = (kbase + j <= qrow) ? sv : -1e30f;
            s[j] = sv;
            mt = fmaxf(mt, sv);
        }

        // online softmax update
        float mnew  = fmaxf(m, mt);
        float scale = __expf(m - mnew);
        m = mnew;
        l *= scale;
#pragma unroll
        for (int i = 0; i < 16; i++) {
            o4[i].x *= scale; o4[i].y *= scale;
            o4[i].z *= scale; o4[i].w *= scale;
        }

#pragma unroll 4
        for (int j = 0; j < 32; j++) {
            float p = __expf(s[j] - m);
            l += p;
            const float4* vr = (const float4*)Vs[j];
#pragma unroll
            for (int i = 0; i < 16; i++) {
                float4 vv = vr[i];
                o4[i].x = fmaf(p, vv.x, o4[i].x);
                o4[i].y = fmaf(p, vv.y, o4[i].y);
                o4[i].z = fmaf(p, vv.z, o4[i].z);
                o4[i].w = fmaf(p, vv.w, o4[i].w);
            }
        }
        __syncthreads();
    }

    float inv = 1.0f / l;
    float* op = out + (size_t)(b * TT + qrow) * CC + h * DD;
#pragma unroll
    for (int i = 0; i < 16; i++) {
        float4 v = make_float4(o4[i].x * inv, o4[i].y * inv,
                               o4[i].z * inv, o4[i].w * inv);
        *(float4*)(op + 4 * i) = v;
    }
}

// ---------------------------------------------------------------------------
extern "C" void kernel_launch(void* const* d_in, const int* in_sizes, int n_in,
                              void* d_out, int out_size)
{
    const float* x     = (const float*)d_in[0];   // [B,T,C]  = [8192,1024]
    const float* w_qkv = (const float*)d_in[1];   // [3C,C]   = [3072,1024]
    const float* w_out = (const float*)d_in[2];   // [C,C]
    const float* b_out = (const float*)d_in[3];   // [C]
    float* out = (float*)d_out;                   // [8192,1024]

    float* qkv = nullptr;
    float* att = nullptr;
    cudaGetSymbolAddress((void**)&qkv, g_qkv);
    cudaGetSymbolAddress((void**)&att, g_att);

    // 1) QKV projection: [8192,1024] x [3072,1024]^T -> [8192,3072]
    {
        dim3 grid(C3 / 128, MTOT / 128);
        gemm_nt<<<grid, 256>>>(x, w_qkv, qkv, nullptr, MTOT, C3, CC);
    }

    // 2) Causal flash attention -> [8192,1024]
    {
        dim3 grid(TT / 128, BB * HH);
        flash_attn<<<grid, 128>>>(qkv, att);
    }

    // 3) Output projection + bias: [8192,1024] x [1024,1024]^T + b
    {
        dim3 grid(CC / 128, MTOT / 128);
        gemm_nt<<<grid, 256>>>(att, w_out, out, b_out, MTOT, CC, CC);
    }
}

// round 2
// speedup vs baseline: 1.3578x; 1.3578x over previous
#include <cuda_runtime.h>
#include <cuda_bf16.h>
#include <math.h>

// Problem constants
#define BB 4
#define TT 2048
#define CC 1024
#define HH 16
#define DD 64
#define C3 3072          // 3*C
#define MTOT 8192        // B*T

// Scratch (device globals — no allocation allowed in kernel_launch)
__device__ float g_qkv[(size_t)MTOT * C3];   // [M, 3C] fp32: q | k | v per row
__device__ float g_att[(size_t)MTOT * CC];   // attention output [M, C]

// bf16 split buffers (hi + lo ≈ fp32 to ~2^-16)
__device__ __nv_bfloat16 g_xh[(size_t)MTOT * CC];
__device__ __nv_bfloat16 g_xl[(size_t)MTOT * CC];
__device__ __nv_bfloat16 g_wqkvh[(size_t)C3 * CC];
__device__ __nv_bfloat16 g_wqkvl[(size_t)C3 * CC];
__device__ __nv_bfloat16 g_wouth[(size_t)CC * CC];
__device__ __nv_bfloat16 g_woutl[(size_t)CC * CC];
__device__ __nv_bfloat16 g_atth[(size_t)MTOT * CC];
__device__ __nv_bfloat16 g_attl[(size_t)MTOT * CC];

// ---------------------------------------------------------------------------
// fp32 -> (bf16 hi, bf16 lo) split. n must be a multiple of 4.
// ---------------------------------------------------------------------------
__global__ __launch_bounds__(256) void split_bf16(
    const float* __restrict__ x,
    __nv_bfloat16* __restrict__ hi, __nv_bfloat16* __restrict__ lo, int n)
{
    int i = blockIdx.x * blockDim.x + threadIdx.x;
    int base = i * 4;
    if (base >= n) return;
    float4 v = *(const float4*)(x + base);

    __nv_bfloat16 h0 = __float2bfloat16(v.x);
    __nv_bfloat16 h1 = __float2bfloat16(v.y);
    __nv_bfloat16 h2 = __float2bfloat16(v.z);
    __nv_bfloat16 h3 = __float2bfloat16(v.w);
    __nv_bfloat16 l0 = __float2bfloat16(v.x - __bfloat162float(h0));
    __nv_bfloat16 l1 = __float2bfloat16(v.y - __bfloat162float(h1));
    __nv_bfloat16 l2 = __float2bfloat16(v.z - __bfloat162float(h2));
    __nv_bfloat16 l3 = __float2bfloat16(v.w - __bfloat162float(h3));

    __nv_bfloat162* hp = (__nv_bfloat162*)(hi + base);
    __nv_bfloat162* lp = (__nv_bfloat162*)(lo + base);
    hp[0] = __nv_bfloat162(h0, h1);
    hp[1] = __nv_bfloat162(h2, h3);
    lp[0] = __nv_bfloat162(l0, l1);
    lp[1] = __nv_bfloat162(l2, l3);
}

// ---------------------------------------------------------------------------
// Tensor-core GEMM (NT): C[m,n] = sum_k A[m,k]*W[n,k] (+ bias[n]), fp32-accurate
// via bf16 split: A ~ Ah+Al, W ~ Wh+Wl; acc += Ah*Wh + Ah*Wl + Al*Wh.
// 128x128 CTA tile, BK=32, 8 warps (2x4), 64x32 warp tile, m16n8k16 MMA.
// ---------------------------------------------------------------------------
#define PADK 40  // padded k-stride in bf16 elements (conflict-free, 16B aligned)

__device__ __forceinline__ void mma_bf16(
    float& c0, float& c1, float& c2, float& c3,
    unsigned a0, unsigned a1, unsigned a2, unsigned a3,
    unsigned b0, unsigned b1)
{
    asm volatile(
        "mma.sync.aligned.m16n8k16.row.col.f32.bf16.bf16.f32 "
        "{%0,%1,%2,%3},{%4,%5,%6,%7},{%8,%9},{%0,%1,%2,%3};"
        : "+f"(c0), "+f"(c1), "+f"(c2), "+f"(c3)
        : "r"(a0), "r"(a1), "r"(a2), "r"(a3), "r"(b0), "r"(b1));
}

__global__ __launch_bounds__(256) void gemm_mma(
    const __nv_bfloat16* __restrict__ Ah, const __nv_bfloat16* __restrict__ Al,
    const __nv_bfloat16* __restrict__ Wh, const __nv_bfloat16* __restrict__ Wl,
    float* __restrict__ C, const float* __restrict__ bias,
    int M, int N, int K)
{
    __shared__ __align__(16) __nv_bfloat16 sAh[128 * PADK];
    __shared__ __align__(16) __nv_bfloat16 sAl[128 * PADK];
    __shared__ __align__(16) __nv_bfloat16 sWh[128 * PADK];
    __shared__ __align__(16) __nv_bfloat16 sWl[128 * PADK];

    const int tid  = threadIdx.x;
    const int lane = tid & 31;
    const int warp = tid >> 5;
    const int wm = (warp >> 2) * 64;   // warp row offset in CTA tile
    const int wn = (warp & 3) * 32;    // warp col offset
    const int brow = blockIdx.y * 128;
    const int bcol = blockIdx.x * 128;

    const int r  = lane >> 2;          // 0..7
    const int cq = lane & 3;           // 0..3

    float acc[4][4][4];
#pragma unroll
    for (int mt = 0; mt < 4; mt++)
#pragma unroll
        for (int nt = 0; nt < 4; nt++)
#pragma unroll
            for (int i = 0; i < 4; i++) acc[mt][nt][i] = 0.0f;

    // gmem loader mapping: 512 uint4 loads per tile pair of iterations
    // idx = tid + i*256 (i=0,1): row = idx>>2 (0..127), col = (idx&3)*8
    uint4 pah[2], pal[2], pwh[2], pwl[2];
#pragma unroll
    for (int i = 0; i < 2; i++) {
        int idx = tid + i * 256;
        int row = idx >> 2;
        int col = (idx & 3) * 8;
        pah[i] = *(const uint4*)(Ah + (size_t)(brow + row) * K + col);
        pal[i] = *(const uint4*)(Al + (size_t)(brow + row) * K + col);
        pwh[i] = *(const uint4*)(Wh + (size_t)(bcol + row) * K + col);
        pwl[i] = *(const uint4*)(Wl + (size_t)(bcol + row) * K + col);
    }

    for (int k0 = 0; k0 < K; k0 += 32) {
        __syncthreads();   // previous compute done before overwriting smem
#pragma unroll
        for (int i = 0; i < 2; i++) {
            int idx = tid + i * 256;
            int row = idx >> 2;
            int col = (idx & 3) * 8;
            *(uint4*)(sAh + row * PADK + col) = pah[i];
            *(uint4*)(sAl + row * PADK + col) = pal[i];
            *(uint4*)(sWh + row * PADK + col) = pwh[i];
            *(uint4*)(sWl + row * PADK + col) = pwl[i];
        }
        __syncthreads();

        if (k0 + 32 < K) {
#pragma unroll
            for (int i = 0; i < 2; i++) {
                int idx = tid + i * 256;
                int row = idx >> 2;
                int col = (idx & 3) * 8 + k0 + 32;
                pah[i] = *(const uint4*)(Ah + (size_t)(brow + row) * K + col);
                pal[i] = *(const uint4*)(Al + (size_t)(brow + row) * K + col);
                pwh[i] = *(const uint4*)(Wh + (size_t)(bcol + row) * K + col);
                pwl[i] = *(const uint4*)(Wl + (size_t)(bcol + row) * K + col);
            }
        }

#pragma unroll
        for (int ks = 0; ks < 32; ks += 16) {
            // B fragments for 4 n-tiles (hi + lo)
            unsigned bh[4][2], bl[4][2];
#pragma unroll
            for (int nt = 0; nt < 4; nt++) {
                int nrow = wn + nt * 8 + r;
                int kc   = ks + cq * 2;
                bh[nt][0] = *(const unsigned*)(sWh + nrow * PADK + kc);
                bh[nt][1] = *(const unsigned*)(sWh + nrow * PADK + kc + 8);
                bl[nt][0] = *(const unsigned*)(sWl + nrow * PADK + kc);
                bl[nt][1] = *(const unsigned*)(sWl + nrow * PADK + kc + 8);
            }
#pragma unroll
            for (int mt = 0; mt < 4; mt++) {
                int mrow = wm + mt * 16 + r;
                int kc   = ks + cq * 2;
                unsigned ah0 = *(const unsigned*)(sAh + mrow * PADK + kc);
                unsigned ah1 = *(const unsigned*)(sAh + (mrow + 8) * PADK + kc);
                unsigned ah2 = *(const unsigned*)(sAh + mrow * PADK + kc + 8);
                unsigned ah3 = *(const unsigned*)(sAh + (mrow + 8) * PADK + kc + 8);
                unsigned al0 = *(const unsigned*)(sAl + mrow * PADK + kc);
                unsigned al1 = *(const unsigned*)(sAl + (mrow + 8) * PADK + kc);
                unsigned al2 = *(const unsigned*)(sAl + mrow * PADK + kc + 8);
                unsigned al3 = *(const unsigned*)(sAl + (mrow + 8) * PADK + kc + 8);
#pragma unroll
                for (int nt = 0; nt < 4; nt++) {
                    float* c = acc[mt][nt];
                    mma_bf16(c[0], c[1], c[2], c[3], ah0, ah1, ah2, ah3, bh[nt][0], bh[nt][1]);
                    mma_bf16(c[0], c[1], c[2], c[3], ah0, ah1, ah2, ah3, bl[nt][0], bl[nt][1]);
                    mma_bf16(c[0], c[1], c[2], c[3], al0, al1, al2, al3, bh[nt][0], bh[nt][1]);
                }
            }
        }
    }

    // Epilogue: c0:(r,2c) c1:(r,2c+1) c2:(r+8,2c) c3:(r+8,2c+1)
#pragma unroll
    for (int mt = 0; mt < 4; mt++) {
#pragma unroll
        for (int nt = 0; nt < 4; nt++) {
            int row0 = brow + wm + mt * 16 + r;
            int col0 = bcol + wn + nt * 8 + cq * 2;
            float b0 = 0.f, b1 = 0.f;
            if (bias != nullptr) { b0 = bias[col0]; b1 = bias[col0 + 1]; }
            float2 v0 = make_float2(acc[mt][nt][0] + b0, acc[mt][nt][1] + b1);
            float2 v1 = make_float2(acc[mt][nt][2] + b0, acc[mt][nt][3] + b1);
            *(float2*)(C + (size_t)row0 * N + col0) = v0;
            *(float2*)(C + (size_t)(row0 + 8) * N + col0) = v1;
        }
    }
}

// ---------------------------------------------------------------------------
// Causal flash attention over the fused qkv buffer (unchanged from R1).
// Grid: (T/128, B*H). 128 threads/CTA, one query row per thread.
// ---------------------------------------------------------------------------
__global__ __launch_bounds__(128) void flash_attn(
    const float* __restrict__ qkv, float* __restrict__ out)
{
    __shared__ float Ks[32][64];
    __shared__ float Vs[32][64];

    int tid = threadIdx.x;
    int qt  = blockIdx.x;
    int bh  = blockIdx.y;
    int b   = bh >> 4;
    int h   = bh & 15;
    int qrow = qt * 128 + tid;

    const float qscale = 0.125f;     // 1/sqrt(64)

    const float* qp = qkv + (size_t)(b * TT + qrow) * C3 + h * DD;
    float4 q4[16];
#pragma unroll
    for (int i = 0; i < 16; i++) {
        float4 v = *(const float4*)(qp + 4 * i);
        q4[i] = make_float4(v.x * qscale, v.y * qscale, v.z * qscale, v.w * qscale);
    }

    float4 o4[16];
#pragma unroll
    for (int i = 0; i < 16; i++) o4[i] = make_float4(0.f, 0.f, 0.f, 0.f);
    float m = -1e30f, l = 0.0f;

    int nkt = 4 * qt + 4;
    for (int kt = 0; kt < nkt; kt++) {
#pragma unroll
        for (int i = 0; i < 4; i++) {
            int idx = tid + i * 128;
            int row = idx >> 4;
            int c4  = (idx & 15) * 4;
            const float* base = qkv + (size_t)(b * TT + kt * 32 + row) * C3 + h * DD + c4;
            *(float4*)&Ks[row][c4] = *(const float4*)(base + CC);
            *(float4*)&Vs[row][c4] = *(const float4*)(base + 2 * CC);
        }
        __syncthreads();

        float s[32];
        float mt = -1e30f;
        int kbase = kt * 32;
#pragma unroll 4
        for (int j = 0; j < 32; j++) {
            const float4* kr = (const float4*)Ks[j];
            float4 acc = make_float4(0.f, 0.f, 0.f, 0.f);
#pragma unroll
            for (int i = 0; i < 16; i++) {
                float4 kv = kr[i];
                acc.x = fmaf(q4[i].x, kv.x, acc.x);
                acc.y = fmaf(q4[i].y, kv.y, acc.y);
                acc.z = fmaf(q4[i].z, kv.z, acc.z);
                acc.w = fmaf(q4[i].w, kv.w, acc.w);
            }
            float sv = (acc.x + acc.y) + (acc.z + acc.w);
            sv = (kbase + j <= qrow) ? sv : -1e30f;
            s[j] = sv;
            mt = fmaxf(mt, sv);
        }

        float mnew  = fmaxf(m, mt);
        float scale = __expf(m - mnew);
        m = mnew;
        l *= scale;
#pragma unroll
        for (int i = 0; i < 16; i++) {
            o4[i].x *= scale; o4[i].y *= scale;
            o4[i].z *= scale; o4[i].w *= scale;
        }

#pragma unroll 4
        for (int j = 0; j < 32; j++) {
            float p = __expf(s[j] - m);
            l += p;
            const float4* vr = (const float4*)Vs[j];
#pragma unroll
            for (int i = 0; i < 16; i++) {
                float4 vv = vr[i];
                o4[i].x = fmaf(p, vv.x, o4[i].x);
                o4[i].y = fmaf(p, vv.y, o4[i].y);
                o4[i].z = fmaf(p, vv.z, o4[i].z);
                o4[i].w = fmaf(p, vv.w, o4[i].w);
            }
        }
        __syncthreads();
    }

    float inv = 1.0f / l;
    float* op = out + (size_t)(b * TT + qrow) * CC + h * DD;
#pragma unroll
    for (int i = 0; i < 16; i++) {
        float4 v = make_float4(o4[i].x * inv, o4[i].y * inv,
                               o4[i].z * inv, o4[i].w * inv);
        *(float4*)(op + 4 * i) = v;
    }
}

// ---------------------------------------------------------------------------
extern "C" void kernel_launch(void* const* d_in, const int* in_sizes, int n_in,
                              void* d_out, int out_size)
{
    const float* x     = (const float*)d_in[0];   // [8192,1024]
    const float* w_qkv = (const float*)d_in[1];   // [3072,1024]
    const float* w_out = (const float*)d_in[2];   // [1024,1024]
    const float* b_out = (const float*)d_in[3];   // [1024]
    float* out = (float*)d_out;                   // [8192,1024]

    float *qkv, *att;
    __nv_bfloat16 *xh, *xl, *wqh, *wql, *woh, *wol, *ath, *atl;
    cudaGetSymbolAddress((void**)&qkv, g_qkv);
    cudaGetSymbolAddress((void**)&att, g_att);
    cudaGetSymbolAddress((void**)&xh,  g_xh);
    cudaGetSymbolAddress((void**)&xl,  g_xl);
    cudaGetSymbolAddress((void**)&wqh, g_wqkvh);
    cudaGetSymbolAddress((void**)&wql, g_wqkvl);
    cudaGetSymbolAddress((void**)&woh, g_wouth);
    cudaGetSymbolAddress((void**)&wol, g_woutl);
    cudaGetSymbolAddress((void**)&ath, g_atth);
    cudaGetSymbolAddress((void**)&atl, g_attl);

    // 0) Split inputs to bf16 hi/lo
    {
        int n1 = MTOT * CC;   // x
        split_bf16<<<(n1 / 4 + 255) / 256, 256>>>(x, xh, xl, n1);
        int n2 = C3 * CC;     // w_qkv
        split_bf16<<<(n2 / 4 + 255) / 256, 256>>>(w_qkv, wqh, wql, n2);
        int n3 = CC * CC;     // w_out
        split_bf16<<<(n3 / 4 + 255) / 256, 256>>>(w_out, woh, wol, n3);
    }

    // 1) QKV projection: [8192,1024] x [3072,1024]^T -> [8192,3072]
    {
        dim3 grid(C3 / 128, MTOT / 128);
        gemm_mma<<<grid, 256>>>(xh, xl, wqh, wql, qkv, nullptr, MTOT, C3, CC);
    }

    // 2) Causal flash attention -> [8192,1024]
    {
        dim3 grid(TT / 128, BB * HH);
        flash_attn<<<grid, 128>>>(qkv, att);
    }

    // 3) Split attention output, then out projection + bias
    {
        int n = MTOT * CC;
        split_bf16<<<(n / 4 + 255) / 256, 256>>>(att, ath, atl, n);
        dim3 grid(CC / 128, MTOT / 128);
        gemm_mma<<<grid, 256>>>(ath, atl, woh, wol, out, b_out, MTOT, CC, CC);
    }
}

// round 3
// speedup vs baseline: 3.0281x; 2.2301x over previous
#include <cuda_runtime.h>
#include <cuda_bf16.h>
#include <math.h>

// Problem constants
#define BB 4
#define TT 2048
#define CC 1024
#define HH 16
#define DD 64
#define C3 3072          // 3*C
#define MTOT 8192        // B*T

// Scratch (device globals — no allocation in kernel_launch)
__device__ __nv_bfloat16 g_xh[(size_t)MTOT * CC];
__device__ __nv_bfloat16 g_xl[(size_t)MTOT * CC];
__device__ __nv_bfloat16 g_wqh[(size_t)C3 * CC];
__device__ __nv_bfloat16 g_wql[(size_t)C3 * CC];
__device__ __nv_bfloat16 g_woh[(size_t)CC * CC];
__device__ __nv_bfloat16 g_wol[(size_t)CC * CC];
__device__ __nv_bfloat16 g_qkvh[(size_t)MTOT * C3];
__device__ __nv_bfloat16 g_qkvl[(size_t)MTOT * C3];
__device__ __nv_bfloat16 g_ath[(size_t)MTOT * CC];
__device__ __nv_bfloat16 g_atl[(size_t)MTOT * CC];

// ---------------------------------------------------------------------------
// Helpers
// ---------------------------------------------------------------------------
__device__ __forceinline__ unsigned sptr(const void* p) {
    return (unsigned)__cvta_generic_to_shared(p);
}

__device__ __forceinline__ void ldsm4(unsigned& r0, unsigned& r1,
                                      unsigned& r2, unsigned& r3, unsigned a) {
    asm volatile("ldmatrix.sync.aligned.m8n8.x4.shared.b16 {%0,%1,%2,%3}, [%4];"
                 : "=r"(r0), "=r"(r1), "=r"(r2), "=r"(r3) : "r"(a));
}

__device__ __forceinline__ void ldsm4t(unsigned& r0, unsigned& r1,
                                       unsigned& r2, unsigned& r3, unsigned a) {
    asm volatile("ldmatrix.sync.aligned.m8n8.x4.trans.shared.b16 {%0,%1,%2,%3}, [%4];"
                 : "=r"(r0), "=r"(r1), "=r"(r2), "=r"(r3) : "r"(a));
}

__device__ __forceinline__ void mma16816(float* c, const unsigned* a,
                                         unsigned b0, unsigned b1) {
    asm volatile(
        "mma.sync.aligned.m16n8k16.row.col.f32.bf16.bf16.f32 "
        "{%0,%1,%2,%3},{%4,%5,%6,%7},{%8,%9},{%0,%1,%2,%3};"
        : "+f"(c[0]), "+f"(c[1]), "+f"(c[2]), "+f"(c[3])
        : "r"(a[0]), "r"(a[1]), "r"(a[2]), "r"(a[3]), "r"(b0), "r"(b1));
}

// fp32 pair -> packed bf16 hi + packed bf16 lo
__device__ __forceinline__ void split2(float x, float y, unsigned& h, unsigned& l) {
    __nv_bfloat162 hh = __floats2bfloat162_rn(x, y);
    float hx = __bfloat162float(hh.x);
    float hy = __bfloat162float(hh.y);
    __nv_bfloat162 ll = __floats2bfloat162_rn(x - hx, y - hy);
    h = *(unsigned*)&hh;
    l = *(unsigned*)&ll;
}

// exact *0.125 on packed bf16x2 (exponent shift)
__device__ __forceinline__ unsigned scale8(unsigned v) {
    __nv_bfloat162 t = *(__nv_bfloat162*)&v;
    __nv_bfloat162 s = __floats2bfloat162_rn(0.125f, 0.125f);
    t = __hmul2(t, s);
    return *(unsigned*)&t;
}

// ---------------------------------------------------------------------------
// fp32 -> (bf16 hi, bf16 lo) split. n multiple of 4.
// ---------------------------------------------------------------------------
__global__ __launch_bounds__(256) void split_bf16(
    const float* __restrict__ x,
    __nv_bfloat16* __restrict__ hi, __nv_bfloat16* __restrict__ lo, int n)
{
    int base = (blockIdx.x * blockDim.x + threadIdx.x) * 4;
    if (base >= n) return;
    float4 v = *(const float4*)(x + base);
    unsigned h01, l01, h23, l23;
    split2(v.x, v.y, h01, l01);
    split2(v.z, v.w, h23, l23);
    *(unsigned*)(hi + base)     = h01;
    *(unsigned*)(hi + base + 2) = h23;
    *(unsigned*)(lo + base)     = l01;
    *(unsigned*)(lo + base + 2) = l23;
}

// ---------------------------------------------------------------------------
// Tensor-core GEMM (NT): C = A*W^T (+bias). bf16 split (hh+hl+lh).
// 128x128 CTA tile, BK=32, 8 warps 2x4, 64x32 warp tile, ldmatrix frags.
// Output: fp32 (Cf) and/or bf16 hi/lo (Ch/Cl).
// ---------------------------------------------------------------------------
#define PADK 40

__global__ __launch_bounds__(256) void gemm_mma(
    const __nv_bfloat16* __restrict__ Ah, const __nv_bfloat16* __restrict__ Al,
    const __nv_bfloat16* __restrict__ Wh, const __nv_bfloat16* __restrict__ Wl,
    float* __restrict__ Cf,
    __nv_bfloat16* __restrict__ Ch, __nv_bfloat16* __restrict__ Cl,
    const float* __restrict__ bias,
    int M, int N, int K)
{
    __shared__ __align__(16) __nv_bfloat16 sAh[128 * PADK];
    __shared__ __align__(16) __nv_bfloat16 sAl[128 * PADK];
    __shared__ __align__(16) __nv_bfloat16 sWh[128 * PADK];
    __shared__ __align__(16) __nv_bfloat16 sWl[128 * PADK];

    const int tid  = threadIdx.x;
    const int lane = tid & 31;
    const int warp = tid >> 5;
    const int wm = (warp >> 2) * 64;
    const int wn = (warp & 3) * 32;
    const int brow = blockIdx.y * 128;
    const int bcol = blockIdx.x * 128;

    float acc[4][4][4];
#pragma unroll
    for (int mt = 0; mt < 4; mt++)
#pragma unroll
        for (int nt = 0; nt < 4; nt++)
#pragma unroll
            for (int i = 0; i < 4; i++) acc[mt][nt][i] = 0.0f;

    uint4 pah[2], pal[2], pwh[2], pwl[2];
#pragma unroll
    for (int i = 0; i < 2; i++) {
        int idx = tid + i * 256;
        int row = idx >> 2;
        int col = (idx & 3) * 8;
        pah[i] = *(const uint4*)(Ah + (size_t)(brow + row) * K + col);
        pal[i] = *(const uint4*)(Al + (size_t)(brow + row) * K + col);
        pwh[i] = *(const uint4*)(Wh + (size_t)(bcol + row) * K + col);
        pwl[i] = *(const uint4*)(Wl + (size_t)(bcol + row) * K + col);
    }

    const int tt  = lane >> 3;
    const int lr8 = lane & 7;

    for (int k0 = 0; k0 < K; k0 += 32) {
        __syncthreads();
#pragma unroll
        for (int i = 0; i < 2; i++) {
            int idx = tid + i * 256;
            int row = idx >> 2;
            int col = (idx & 3) * 8;
            *(uint4*)(sAh + row * PADK + col) = pah[i];
            *(uint4*)(sAl + row * PADK + col) = pal[i];
            *(uint4*)(sWh + row * PADK + col) = pwh[i];
            *(uint4*)(sWl + row * PADK + col) = pwl[i];
        }
        __syncthreads();

        if (k0 + 32 < K) {
#pragma unroll
            for (int i = 0; i < 2; i++) {
                int idx = tid + i * 256;
                int row = idx >> 2;
                int col = (idx & 3) * 8 + k0 + 32;
                pah[i] = *(const uint4*)(Ah + (size_t)(brow + row) * K + col);
                pal[i] = *(const uint4*)(Al + (size_t)(brow + row) * K + col);
                pwh[i] = *(const uint4*)(Wh + (size_t)(bcol + row) * K + col);
                pwl[i] = *(const uint4*)(Wl + (size_t)(bcol + row) * K + col);
            }
        }

#pragma unroll
        for (int ks = 0; ks < 32; ks += 16) {
            unsigned bh[4][2], bl[4][2];
#pragma unroll
            for (int i = 0; i < 2; i++) {
                int nrow = wn + (2 * i + (tt >> 1)) * 8 + lr8;
                int ncol = ks + (tt & 1) * 8;
                ldsm4(bh[2 * i][0], bh[2 * i][1], bh[2 * i + 1][0], bh[2 * i + 1][1],
                      sptr(sWh + nrow * PADK + ncol));
                ldsm4(bl[2 * i][0], bl[2 * i][1], bl[2 * i + 1][0], bl[2 * i + 1][1],
                      sptr(sWl + nrow * PADK + ncol));
            }
#pragma unroll
            for (int mt = 0; mt < 4; mt++) {
                unsigned ah[4], al[4];
                int arow = wm + mt * 16 + (tt & 1) * 8 + lr8;
                int acol = ks + (tt >> 1) * 8;
                ldsm4(ah[0], ah[1], ah[2], ah[3], sptr(sAh + arow * PADK + acol));
                ldsm4(al[0], al[1], al[2], al[3], sptr(sAl + arow * PADK + acol));
#pragma unroll
                for (int nt = 0; nt < 4; nt++) {
                    mma16816(acc[mt][nt], ah, bh[nt][0], bh[nt][1]);
                    mma16816(acc[mt][nt], ah, bl[nt][0], bl[nt][1]);
                    mma16816(acc[mt][nt], al, bh[nt][0], bh[nt][1]);
                }
            }
        }
    }

    const int r  = lane >> 2;
    const int cq = lane & 3;
#pragma unroll
    for (int mt = 0; mt < 4; mt++) {
#pragma unroll
        for (int nt = 0; nt < 4; nt++) {
            int row0 = brow + wm + mt * 16 + r;
            int col0 = bcol + wn + nt * 8 + cq * 2;
            float b0 = 0.f, b1 = 0.f;
            if (bias != nullptr) { b0 = bias[col0]; b1 = bias[col0 + 1]; }
            float v0 = acc[mt][nt][0] + b0, v1 = acc[mt][nt][1] + b1;
            float v2 = acc[mt][nt][2] + b0, v3 = acc[mt][nt][3] + b1;
            if (Cf != nullptr) {
                *(float2*)(Cf + (size_t)row0 * N + col0)       = make_float2(v0, v1);
                *(float2*)(Cf + (size_t)(row0 + 8) * N + col0) = make_float2(v2, v3);
            }
            if (Ch != nullptr) {
                unsigned h01, l01, h23, l23;
                split2(v0, v1, h01, l01);
                split2(v2, v3, h23, l23);
                *(unsigned*)(Ch + (size_t)row0 * N + col0)       = h01;
                *(unsigned*)(Cl + (size_t)row0 * N + col0)       = l01;
                *(unsigned*)(Ch + (size_t)(row0 + 8) * N + col0) = h23;
                *(unsigned*)(Cl + (size_t)(row0 + 8) * N + col0) = l23;
            }
        }
    }
}

// ---------------------------------------------------------------------------
// Tensor-core causal flash attention, split-bf16.
// Grid (16, 64): x = q-tile (reversed for balance), y = b*16+h.
// Br=128, Bc=64, 8 warps; warp w owns rows w*16..w*16+15.
// ---------------------------------------------------------------------------
#define SKP 72   // smem row stride in bf16: 144B rows, 16B-aligned, LDSM conflict-free

__global__ __launch_bounds__(256) void flash_attn_mma(
    const __nv_bfloat16* __restrict__ qkvh,
    const __nv_bfloat16* __restrict__ qkvl,
    __nv_bfloat16* __restrict__ outh,
    __nv_bfloat16* __restrict__ outl)
{
    __shared__ __align__(16) __nv_bfloat16 sKh[64 * SKP];
    __shared__ __align__(16) __nv_bfloat16 sKl[64 * SKP];
    __shared__ __align__(16) __nv_bfloat16 sVh[64 * SKP];
    __shared__ __align__(16) __nv_bfloat16 sVl[64 * SKP];

    const int tid  = threadIdx.x;
    const int lane = tid & 31;
    const int w    = tid >> 5;
    const int qt   = (gridDim.x - 1) - blockIdx.x;   // heavy tiles first
    const int bh   = blockIdx.y;
    const int b    = bh >> 4;
    const int h    = bh & 15;

    const int tt  = lane >> 3;
    const int lr8 = lane & 7;
    const int r   = lane >> 2;
    const int cq  = lane & 3;

    const int rowr  = qt * 128 + w * 16 + r;   // global q row (within sequence)
    const int rowr8 = rowr + 8;

    // ---- stage Q (two 64-row halves) and build Q fragments ----
    unsigned qah[4][4], qal[4][4];
#pragma unroll
    for (int half = 0; half < 2; half++) {
        __syncthreads();
#pragma unroll
        for (int i = 0; i < 2; i++) {
            int idx = tid + i * 256;
            int row = idx >> 3;
            int c8  = (idx & 7) * 8;
            size_t g = (size_t)(b * TT + qt * 128 + half * 64 + row) * C3 + h * DD + c8;
            *(uint4*)(sKh + row * SKP + c8) = *(const uint4*)(qkvh + g);
            *(uint4*)(sKl + row * SKP + c8) = *(const uint4*)(qkvl + g);
        }
        __syncthreads();
        if ((w >> 2) == half) {
            int wq = (w & 3) * 16;
#pragma unroll
            for (int kc = 0; kc < 4; kc++) {
                int qrow = wq + (tt & 1) * 8 + lr8;
                int qcol = kc * 16 + (tt >> 1) * 8;
                ldsm4(qah[kc][0], qah[kc][1], qah[kc][2], qah[kc][3],
                      sptr(sKh + qrow * SKP + qcol));
                ldsm4(qal[kc][0], qal[kc][1], qal[kc][2], qal[kc][3],
                      sptr(sKl + qrow * SKP + qcol));
#pragma unroll
                for (int j = 0; j < 4; j++) {
                    qah[kc][j] = scale8(qah[kc][j]);   // fold 1/sqrt(D)=0.125 (exact)
                    qal[kc][j] = scale8(qal[kc][j]);
                }
            }
        }
    }

    // ---- online softmax state ----
    float o[8][4];
#pragma unroll
    for (int nt = 0; nt < 8; nt++)
#pragma unroll
        for (int j = 0; j < 4; j++) o[nt][j] = 0.0f;
    float m_r = -1e30f, m_r8 = -1e30f;
    float l_r = 0.0f,   l_r8 = 0.0f;

    const int nkt = 2 * qt + 2;

    // prefetch tile 0
    uint4 pkh[2], pkl[2], pvh[2], pvl[2];
    {
        size_t base = (size_t)(b * TT) * C3 + h * DD;
#pragma unroll
        for (int i = 0; i < 2; i++) {
            int row = (tid >> 3) + i * 32;
            int c8  = (tid & 7) * 8;
            size_t gk = base + (size_t)row * C3 + CC + c8;
            size_t gv = base + (size_t)row * C3 + 2 * CC + c8;
            pkh[i] = *(const uint4*)(qkvh + gk);
            pkl[i] = *(const uint4*)(qkvl + gk);
            pvh[i] = *(const uint4*)(qkvh + gv);
            pvl[i] = *(const uint4*)(qkvl + gv);
        }
    }

    for (int kt = 0; kt < nkt; kt++) {
        __syncthreads();
#pragma unroll
        for (int i = 0; i < 2; i++) {
            int row = (tid >> 3) + i * 32;
            int c8  = (tid & 7) * 8;
            *(uint4*)(sKh + row * SKP + c8) = pkh[i];
            *(uint4*)(sKl + row * SKP + c8) = pkl[i];
            *(uint4*)(sVh + row * SKP + c8) = pvh[i];
            *(uint4*)(sVl + row * SKP + c8) = pvl[i];
        }
        __syncthreads();

        if (kt + 1 < nkt) {
            size_t base = (size_t)(b * TT + (kt + 1) * 64) * C3 + h * DD;
#pragma unroll
            for (int i = 0; i < 2; i++) {
                int row = (tid >> 3) + i * 32;
                int c8  = (tid & 7) * 8;
                size_t gk = base + (size_t)row * C3 + CC + c8;
                size_t gv = base + (size_t)row * C3 + 2 * CC + c8;
                pkh[i] = *(const uint4*)(qkvh + gk);
                pkl[i] = *(const uint4*)(qkvl + gk);
                pvh[i] = *(const uint4*)(qkvh + gv);
                pvl[i] = *(const uint4*)(qkvl + gv);
            }
        }

        // warp active iff tile has any unmasked key for this warp's rows
        if (kt * 64 <= qt * 128 + w * 16 + 15) {
            // ---- scores: S = (Qh+Ql)(Kh+Kl)^T (drop Ql*Kl) ----
            float s[8][4];
#pragma unroll
            for (int nt = 0; nt < 8; nt++)
#pragma unroll
                for (int j = 0; j < 4; j++) s[nt][j] = 0.0f;

#pragma unroll
            for (int kc = 0; kc < 4; kc++) {
                unsigned kbh[8][2], kbl[8][2];
#pragma unroll
                for (int i = 0; i < 4; i++) {
                    int nrow = (2 * i + (tt >> 1)) * 8 + lr8;
                    int ncol = kc * 16 + (tt & 1) * 8;
                    ldsm4(kbh[2 * i][0], kbh[2 * i][1], kbh[2 * i + 1][0], kbh[2 * i + 1][1],
                          sptr(sKh + nrow * SKP + ncol));
                    ldsm4(kbl[2 * i][0], kbl[2 * i][1], kbl[2 * i + 1][0], kbl[2 * i + 1][1],
                          sptr(sKl + nrow * SKP + ncol));
                }
#pragma unroll
                for (int nt = 0; nt < 8; nt++) {
                    mma16816(s[nt], qah[kc], kbh[nt][0], kbh[nt][1]);
                    mma16816(s[nt], qah[kc], kbl[nt][0], kbl[nt][1]);
                    mma16816(s[nt], qal[kc], kbh[nt][0], kbh[nt][1]);
                }
            }

            // ---- causal mask (only tiles that can cross the diagonal) ----
            if (kt >= 2 * qt) {
                int colb = kt * 64 + cq * 2;
#pragma unroll
                for (int nt = 0; nt < 8; nt++) {
                    int c0 = colb + nt * 8;
                    if (c0 > rowr)      s[nt][0] = -1e30f;
                    if (c0 + 1 > rowr)  s[nt][1] = -1e30f;
                    if (c0 > rowr8)     s[nt][2] = -1e30f;
                    if (c0 + 1 > rowr8) s[nt][3] = -1e30f;
                }
            }

            // ---- online softmax ----
            float mr = -1e30f, mr8 = -1e30f;
#pragma unroll
            for (int nt = 0; nt < 8; nt++) {
                mr  = fmaxf(mr,  fmaxf(s[nt][0], s[nt][1]));
                mr8 = fmaxf(mr8, fmaxf(s[nt][2], s[nt][3]));
            }
            mr  = fmaxf(mr,  __shfl_xor_sync(0xffffffffu, mr, 1));
            mr  = fmaxf(mr,  __shfl_xor_sync(0xffffffffu, mr, 2));
            mr8 = fmaxf(mr8, __shfl_xor_sync(0xffffffffu, mr8, 1));
            mr8 = fmaxf(mr8, __shfl_xor_sync(0xffffffffu, mr8, 2));

            float mn  = fmaxf(m_r, mr);
            float mn8 = fmaxf(m_r8, mr8);
            float ar  = __expf(m_r - mn);
            float ar8 = __expf(m_r8 - mn8);
            m_r = mn; m_r8 = mn8;

            float lsr = 0.f, lsr8 = 0.f;
#pragma unroll
            for (int nt = 0; nt < 8; nt++) {
                float p0 = __expf(s[nt][0] - m_r);
                float p1 = __expf(s[nt][1] - m_r);
                float p2 = __expf(s[nt][2] - m_r8);
                float p3 = __expf(s[nt][3] - m_r8);
                lsr += p0 + p1; lsr8 += p2 + p3;
                s[nt][0] = p0; s[nt][1] = p1; s[nt][2] = p2; s[nt][3] = p3;
                o[nt][0] *= ar; o[nt][1] *= ar; o[nt][2] *= ar8; o[nt][3] *= ar8;
            }
            l_r  = l_r  * ar  + lsr;
            l_r8 = l_r8 * ar8 + lsr8;

            // ---- PV: O += (Ph+Pl)(Vh+Vl) (drop Pl*Vl) ----
#pragma unroll
            for (int kc = 0; kc < 4; kc++) {
                unsigned pah[4], pal[4];
                split2(s[2 * kc][0],     s[2 * kc][1],     pah[0], pal[0]);
                split2(s[2 * kc][2],     s[2 * kc][3],     pah[1], pal[1]);
                split2(s[2 * kc + 1][0], s[2 * kc + 1][1], pah[2], pal[2]);
                split2(s[2 * kc + 1][2], s[2 * kc + 1][3], pah[3], pal[3]);

                unsigned vbh[8][2], vbl[8][2];
#pragma unroll
                for (int i = 0; i < 4; i++) {
                    int vrow = kc * 16 + (tt & 1) * 8 + lr8;
                    int vcol = (2 * i + (tt >> 1)) * 8;
                    ldsm4t(vbh[2 * i][0], vbh[2 * i][1], vbh[2 * i + 1][0], vbh[2 * i + 1][1],
                           sptr(sVh + vrow * SKP + vcol));
                    ldsm4t(vbl[2 * i][0], vbl[2 * i][1], vbl[2 * i + 1][0], vbl[2 * i + 1][1],
                           sptr(sVl + vrow * SKP + vcol));
                }
#pragma unroll
                for (int nt = 0; nt < 8; nt++) {
                    mma16816(o[nt], pah, vbh[nt][0], vbh[nt][1]);
                    mma16816(o[nt], pah, vbl[nt][0], vbl[nt][1]);
                    mma16816(o[nt], pal, vbh[nt][0], vbh[nt][1]);
                }
            }
        }
    }

    // ---- finalize: divide by l, split to hi/lo, store ----
    l_r  += __shfl_xor_sync(0xffffffffu, l_r, 1);
    l_r  += __shfl_xor_sync(0xffffffffu, l_r, 2);
    l_r8 += __shfl_xor_sync(0xffffffffu, l_r8, 1);
    l_r8 += __shfl_xor_sync(0xffffffffu, l_r8, 2);
    float inv  = 1.0f / l_r;
    float inv8 = 1.0f / l_r8;

#pragma unroll
    for (int nt = 0; nt < 8; nt++) {
        unsigned h01, l01, h23, l23;
        split2(o[nt][0] * inv,  o[nt][1] * inv,  h01, l01);
        split2(o[nt][2] * inv8, o[nt][3] * inv8, h23, l23);
        size_t a0 = (size_t)(b * TT + rowr)  * CC + h * DD + nt * 8 + cq * 2;
        size_t a1 = (size_t)(b * TT + rowr8) * CC + h * DD + nt * 8 + cq * 2;
        *(unsigned*)(outh + a0) = h01;
        *(unsigned*)(outl + a0) = l01;
        *(unsigned*)(outh + a1) = h23;
        *(unsigned*)(outl + a1) = l23;
    }
}

// ---------------------------------------------------------------------------
extern "C" void kernel_launch(void* const* d_in, const int* in_sizes, int n_in,
                              void* d_out, int out_size)
{
    const float* x     = (const float*)d_in[0];
    const float* w_qkv = (const float*)d_in[1];
    const float* w_out = (const float*)d_in[2];
    const float* b_out = (const float*)d_in[3];
    float* out = (float*)d_out;

    __nv_bfloat16 *xh, *xl, *wqh, *wql, *woh, *wol, *qkvh, *qkvl, *ath, *atl;
    cudaGetSymbolAddress((void**)&xh,   g_xh);
    cudaGetSymbolAddress((void**)&xl,   g_xl);
    cudaGetSymbolAddress((void**)&wqh,  g_wqh);
    cudaGetSymbolAddress((void**)&wql,  g_wql);
    cudaGetSymbolAddress((void**)&woh,  g_woh);
    cudaGetSymbolAddress((void**)&wol,  g_wol);
    cudaGetSymbolAddress((void**)&qkvh, g_qkvh);
    cudaGetSymbolAddress((void**)&qkvl, g_qkvl);
    cudaGetSymbolAddress((void**)&ath,  g_ath);
    cudaGetSymbolAddress((void**)&atl,  g_atl);

    // 0) split inputs
    {
        int n1 = MTOT * CC;
        split_bf16<<<(n1 / 4 + 255) / 256, 256>>>(x, xh, xl, n1);
        int n2 = C3 * CC;
        split_bf16<<<(n2 / 4 + 255) / 256, 256>>>(w_qkv, wqh, wql, n2);
        int n3 = CC * CC;
        split_bf16<<<(n3 / 4 + 255) / 256, 256>>>(w_out, woh, wol, n3);
    }

    // 1) QKV projection -> bf16 hi/lo directly
    {
        dim3 grid(C3 / 128, MTOT / 128);
        gemm_mma<<<grid, 256>>>(xh, xl, wqh, wql,
                                nullptr, qkvh, qkvl, nullptr, MTOT, C3, CC);
    }

    // 2) causal flash attention (tensor cores) -> bf16 hi/lo
    {
        dim3 grid(TT / 128, BB * HH);
        flash_attn_mma<<<grid, 256>>>(qkvh, qkvl, ath, atl);
    }

    // 3) out projection + bias -> fp32 output
    {
        dim3 grid(CC / 128, MTOT / 128);
        gemm_mma<<<grid, 256>>>(ath, atl, woh, wol,
                                out, nullptr, nullptr, b_out, MTOT, CC, CC);
    }
}